// round 2
// baseline (speedup 1.0000x reference)
#include <cuda_runtime.h>
#include <cstddef>

#define N_NODES 50000
#define N_EDGES 200000
#define NB      64
#define DIN_N   64
#define DIN_E   16
#define DN      128
#define DE      64
#define DHID    64
#define NL      6

#define TE 32
#define HS_STRIDE 136
#define E_STRIDE  68

// ---------------- scratch (no allocation allowed -> __device__ globals) ----------------
__device__ float g_h[(size_t)N_NODES * DN];      // 25.6 MB
__device__ float g_e[(size_t)N_EDGES * DE];      // 51.2 MB
__device__ float g_m[(size_t)N_NODES * DE];      // 12.8 MB
__device__ float g_deg[N_NODES];
__device__ float g_gsum[NB * DN];
__device__ float g_gcnt[NB];
__device__ float g_rtmp[NB * DN];

// ---------------- helpers ----------------
__global__ void zero_kernel(float* p, int n) {
    int i = blockIdx.x * blockDim.x + threadIdx.x;
    if (i < n) p[i] = 0.f;
}

__global__ void deg_kernel(const int* __restrict__ dst) {
    int i = blockIdx.x * blockDim.x + threadIdx.x;
    if (i < N_EDGES) atomicAdd(&g_deg[dst[i]], 1.f);
}

// h = x @ Wx + b    x:[N,64] Wx:[64,128]
__global__ void node_enc_kernel(const float* __restrict__ x,
                                const float* __restrict__ w,
                                const float* __restrict__ b) {
    __shared__ float xs[DIN_N];
    int nidx = blockIdx.x;
    int j = threadIdx.x;                 // 0..127
    if (j < DIN_N) xs[j] = x[(size_t)nidx * DIN_N + j];
    __syncthreads();
    float acc = b[j];
#pragma unroll 8
    for (int k = 0; k < DIN_N; k++) acc = fmaf(xs[k], w[k * DN + j], acc);
    g_h[(size_t)nidx * DN + j] = acc;
}

// e = ea @ We + b    ea:[E,16] We:[16,64]   4 edges / block
__global__ void edge_enc_kernel(const float* __restrict__ ea,
                                const float* __restrict__ w,
                                const float* __restrict__ b) {
    __shared__ float es[4][DIN_E];
    int base = blockIdx.x * 4;
    int tid = threadIdx.x;
    if (tid < 64) es[tid >> 4][tid & 15] = ea[(size_t)base * DIN_E + tid];
    __syncthreads();
    int i = tid >> 6;       // 0..3
    int j = tid & 63;       // 0..63
    float acc = b[j];
#pragma unroll
    for (int k = 0; k < DIN_E; k++) acc = fmaf(es[i][k], w[k * DE + j], acc);
    g_e[(size_t)(base + i) * DE + j] = acc;
}

// ---------------- per-layer edge update ----------------
// e_in = [h[src], h[dst], e + h[src]@mw] ; e += relu(e_in@w1+b1)@w2 + b2 ; scatter-add into m[dst]
__global__ void __launch_bounds__(256, 1)
edge_layer_kernel(const int* __restrict__ src, const int* __restrict__ dst,
                  const float* __restrict__ mw, const float* __restrict__ w1,
                  const float* __restrict__ b1, const float* __restrict__ w2,
                  const float* __restrict__ b2) {
    extern __shared__ float sm[];
    float* mw_s = sm;                               // 128*64
    float* w1_s = mw_s + DN * DE;                   // 320*64
    float* w2_s = w1_s + (DE + 2 * DN) * DHID;      // 64*64
    float* b1_s = w2_s + DHID * DE;                 // 64
    float* b2_s = b1_s + DHID;                      // 64
    float* hs_s = b2_s + DE;                        // 32*136
    float* hd_s = hs_s + TE * HS_STRIDE;            // 32*136
    float* e_s  = hd_s + TE * HS_STRIDE;            // 32*68
    float* t_s  = e_s  + TE * E_STRIDE;             // 32*68
    float* u_s  = t_s  + TE * E_STRIDE;             // 32*68

    const int tid = threadIdx.x;
    for (int idx = tid; idx < DN * DE; idx += 256) mw_s[idx] = mw[idx];
    for (int idx = tid; idx < (DE + 2 * DN) * DHID; idx += 256) w1_s[idx] = w1[idx];
    for (int idx = tid; idx < DHID * DE; idx += 256) w2_s[idx] = w2[idx];
    if (tid < DHID) b1_s[tid] = b1[tid];
    if (tid < DE)   b2_s[tid] = b2[tid];
    __syncthreads();

    const int i  = tid >> 3;     // edge-in-tile 0..31
    const int r  = tid & 7;      // 0..7
    const int j0 = r << 3;       // output col group (8 cols)

    for (int tile = blockIdx.x * TE; tile < N_EDGES; tile += gridDim.x * TE) {
        const int eidx = tile + i;
        const int s = src[eidx];
        const int d = dst[eidx];
        {
            const float4* hsp = (const float4*)(g_h + (size_t)s * DN);
            const float4* hdp = (const float4*)(g_h + (size_t)d * DN);
#pragma unroll
            for (int q = 0; q < 4; q++) {
                float4 v = hsp[r + 8 * q];
                int c = (r + 8 * q) << 2;
                hs_s[i * HS_STRIDE + c]     = v.x;
                hs_s[i * HS_STRIDE + c + 1] = v.y;
                hs_s[i * HS_STRIDE + c + 2] = v.z;
                hs_s[i * HS_STRIDE + c + 3] = v.w;
                float4 u = hdp[r + 8 * q];
                hd_s[i * HS_STRIDE + c]     = u.x;
                hd_s[i * HS_STRIDE + c + 1] = u.y;
                hd_s[i * HS_STRIDE + c + 2] = u.z;
                hd_s[i * HS_STRIDE + c + 3] = u.w;
            }
            const float4* ep = (const float4*)(g_e + (size_t)eidx * DE);
#pragma unroll
            for (int q = 0; q < 2; q++) {
                float4 v = ep[r * 2 + q];
                int c = (r * 2 + q) << 2;
                e_s[i * E_STRIDE + c]     = v.x;
                e_s[i * E_STRIDE + c + 1] = v.y;
                e_s[i * E_STRIDE + c + 2] = v.z;
                e_s[i * E_STRIDE + c + 3] = v.w;
            }
        }
        __syncthreads();

        // -------- msg = hs @ mw ; t = e + msg --------
        float acc[8];
#pragma unroll
        for (int c = 0; c < 8; c++) acc[c] = 0.f;
#pragma unroll 8
        for (int k = 0; k < DN; k++) {
            float a = hs_s[i * HS_STRIDE + k];
            float4 wa = *(const float4*)(mw_s + k * DE + j0);
            float4 wb = *(const float4*)(mw_s + k * DE + j0 + 4);
            acc[0] = fmaf(a, wa.x, acc[0]); acc[1] = fmaf(a, wa.y, acc[1]);
            acc[2] = fmaf(a, wa.z, acc[2]); acc[3] = fmaf(a, wa.w, acc[3]);
            acc[4] = fmaf(a, wb.x, acc[4]); acc[5] = fmaf(a, wb.y, acc[5]);
            acc[6] = fmaf(a, wb.z, acc[6]); acc[7] = fmaf(a, wb.w, acc[7]);
        }
#pragma unroll
        for (int c = 0; c < 8; c++)
            t_s[i * E_STRIDE + j0 + c] = e_s[i * E_STRIDE + j0 + c] + acc[c];
        __syncthreads();

        // -------- u = relu([hs,hd,t] @ w1 + b1) --------
#pragma unroll
        for (int c = 0; c < 8; c++) acc[c] = 0.f;
#pragma unroll 8
        for (int k = 0; k < DN; k++) {
            float a = hs_s[i * HS_STRIDE + k];
            float4 wa = *(const float4*)(w1_s + k * DHID + j0);
            float4 wb = *(const float4*)(w1_s + k * DHID + j0 + 4);
            acc[0] = fmaf(a, wa.x, acc[0]); acc[1] = fmaf(a, wa.y, acc[1]);
            acc[2] = fmaf(a, wa.z, acc[2]); acc[3] = fmaf(a, wa.w, acc[3]);
            acc[4] = fmaf(a, wb.x, acc[4]); acc[5] = fmaf(a, wb.y, acc[5]);
            acc[6] = fmaf(a, wb.z, acc[6]); acc[7] = fmaf(a, wb.w, acc[7]);
        }
#pragma unroll 8
        for (int k = 0; k < DN; k++) {
            float a = hd_s[i * HS_STRIDE + k];
            float4 wa = *(const float4*)(w1_s + (DN + k) * DHID + j0);
            float4 wb = *(const float4*)(w1_s + (DN + k) * DHID + j0 + 4);
            acc[0] = fmaf(a, wa.x, acc[0]); acc[1] = fmaf(a, wa.y, acc[1]);
            acc[2] = fmaf(a, wa.z, acc[2]); acc[3] = fmaf(a, wa.w, acc[3]);
            acc[4] = fmaf(a, wb.x, acc[4]); acc[5] = fmaf(a, wb.y, acc[5]);
            acc[6] = fmaf(a, wb.z, acc[6]); acc[7] = fmaf(a, wb.w, acc[7]);
        }
#pragma unroll 8
        for (int k = 0; k < DE; k++) {
            float a = t_s[i * E_STRIDE + k];
            float4 wa = *(const float4*)(w1_s + (2 * DN + k) * DHID + j0);
            float4 wb = *(const float4*)(w1_s + (2 * DN + k) * DHID + j0 + 4);
            acc[0] = fmaf(a, wa.x, acc[0]); acc[1] = fmaf(a, wa.y, acc[1]);
            acc[2] = fmaf(a, wa.z, acc[2]); acc[3] = fmaf(a, wa.w, acc[3]);
            acc[4] = fmaf(a, wb.x, acc[4]); acc[5] = fmaf(a, wb.y, acc[5]);
            acc[6] = fmaf(a, wb.z, acc[6]); acc[7] = fmaf(a, wb.w, acc[7]);
        }
#pragma unroll
        for (int c = 0; c < 8; c++)
            u_s[i * E_STRIDE + j0 + c] = fmaxf(acc[c] + b1_s[j0 + c], 0.f);
        __syncthreads();

        // -------- e_new = e + u @ w2 + b2 ; store + scatter-add --------
#pragma unroll
        for (int c = 0; c < 8; c++) acc[c] = 0.f;
#pragma unroll 8
        for (int k = 0; k < DHID; k++) {
            float a = u_s[i * E_STRIDE + k];
            float4 wa = *(const float4*)(w2_s + k * DE + j0);
            float4 wb = *(const float4*)(w2_s + k * DE + j0 + 4);
            acc[0] = fmaf(a, wa.x, acc[0]); acc[1] = fmaf(a, wa.y, acc[1]);
            acc[2] = fmaf(a, wa.z, acc[2]); acc[3] = fmaf(a, wa.w, acc[3]);
            acc[4] = fmaf(a, wb.x, acc[4]); acc[5] = fmaf(a, wb.y, acc[5]);
            acc[6] = fmaf(a, wb.z, acc[6]); acc[7] = fmaf(a, wb.w, acc[7]);
        }
        float* eo = g_e + (size_t)eidx * DE + j0;
        float* mo = g_m + (size_t)d * DE + j0;
#pragma unroll
        for (int c = 0; c < 8; c++) {
            float en = e_s[i * E_STRIDE + j0 + c] + acc[c] + b2_s[j0 + c];
            eo[c] = en;
            atomicAdd(mo + c, en);
        }
        __syncthreads();
    }
}

// ---------------- per-layer node update ----------------
// h += relu([h, m/deg] @ w1 + b1) @ w2 + b2
__global__ void __launch_bounds__(256, 1)
node_layer_kernel(const float* __restrict__ w1, const float* __restrict__ b1,
                  const float* __restrict__ w2, const float* __restrict__ b2) {
    extern __shared__ float sm[];
    float* w1_s = sm;                             // 192*64
    float* w2_s = w1_s + (DN + DE) * DHID;        // 64*128
    float* b1_s = w2_s + DHID * DN;               // 64
    float* b2_s = b1_s + DHID;                    // 128
    float* h_s  = b2_s + DN;                      // 32*136
    float* m_s  = h_s + TE * HS_STRIDE;           // 32*68
    float* u_s  = m_s + TE * E_STRIDE;            // 32*68

    const int tid = threadIdx.x;
    for (int idx = tid; idx < (DN + DE) * DHID; idx += 256) w1_s[idx] = w1[idx];
    for (int idx = tid; idx < DHID * DN; idx += 256) w2_s[idx] = w2[idx];
    if (tid < DHID) b1_s[tid] = b1[tid];
    if (tid < DN)   b2_s[tid] = b2[tid];
    __syncthreads();

    const int i  = tid >> 3;
    const int r  = tid & 7;
    const int j0 = r << 3;

    for (int tile = blockIdx.x * TE; tile < N_NODES; tile += gridDim.x * TE) {
        const int node = tile + i;
        const bool ok = node < N_NODES;
        if (ok) {
            const float4* hp = (const float4*)(g_h + (size_t)node * DN);
#pragma unroll
            for (int q = 0; q < 4; q++) {
                float4 v = hp[r + 8 * q];
                int c = (r + 8 * q) << 2;
                h_s[i * HS_STRIDE + c]     = v.x;
                h_s[i * HS_STRIDE + c + 1] = v.y;
                h_s[i * HS_STRIDE + c + 2] = v.z;
                h_s[i * HS_STRIDE + c + 3] = v.w;
            }
            const float inv = 1.f / fmaxf(g_deg[node], 1.f);
            const float4* mp = (const float4*)(g_m + (size_t)node * DE);
#pragma unroll
            for (int q = 0; q < 2; q++) {
                float4 v = mp[r * 2 + q];
                int c = (r * 2 + q) << 2;
                m_s[i * E_STRIDE + c]     = v.x * inv;
                m_s[i * E_STRIDE + c + 1] = v.y * inv;
                m_s[i * E_STRIDE + c + 2] = v.z * inv;
                m_s[i * E_STRIDE + c + 3] = v.w * inv;
            }
        } else {
#pragma unroll
            for (int q = 0; q < 4; q++) {
                int c = (r + 8 * q) << 2;
                h_s[i * HS_STRIDE + c] = 0.f; h_s[i * HS_STRIDE + c + 1] = 0.f;
                h_s[i * HS_STRIDE + c + 2] = 0.f; h_s[i * HS_STRIDE + c + 3] = 0.f;
            }
#pragma unroll
            for (int q = 0; q < 2; q++) {
                int c = (r * 2 + q) << 2;
                m_s[i * E_STRIDE + c] = 0.f; m_s[i * E_STRIDE + c + 1] = 0.f;
                m_s[i * E_STRIDE + c + 2] = 0.f; m_s[i * E_STRIDE + c + 3] = 0.f;
            }
        }
        __syncthreads();

        // u = relu([h, m] @ w1 + b1)
        float acc[8];
#pragma unroll
        for (int c = 0; c < 8; c++) acc[c] = 0.f;
#pragma unroll 8
        for (int k = 0; k < DN; k++) {
            float a = h_s[i * HS_STRIDE + k];
            float4 wa = *(const float4*)(w1_s + k * DHID + j0);
            float4 wb = *(const float4*)(w1_s + k * DHID + j0 + 4);
            acc[0] = fmaf(a, wa.x, acc[0]); acc[1] = fmaf(a, wa.y, acc[1]);
            acc[2] = fmaf(a, wa.z, acc[2]); acc[3] = fmaf(a, wa.w, acc[3]);
            acc[4] = fmaf(a, wb.x, acc[4]); acc[5] = fmaf(a, wb.y, acc[5]);
            acc[6] = fmaf(a, wb.z, acc[6]); acc[7] = fmaf(a, wb.w, acc[7]);
        }
#pragma unroll 8
        for (int k = 0; k < DE; k++) {
            float a = m_s[i * E_STRIDE + k];
            float4 wa = *(const float4*)(w1_s + (DN + k) * DHID + j0);
            float4 wb = *(const float4*)(w1_s + (DN + k) * DHID + j0 + 4);
            acc[0] = fmaf(a, wa.x, acc[0]); acc[1] = fmaf(a, wa.y, acc[1]);
            acc[2] = fmaf(a, wa.z, acc[2]); acc[3] = fmaf(a, wa.w, acc[3]);
            acc[4] = fmaf(a, wb.x, acc[4]); acc[5] = fmaf(a, wb.y, acc[5]);
            acc[6] = fmaf(a, wb.z, acc[6]); acc[7] = fmaf(a, wb.w, acc[7]);
        }
#pragma unroll
        for (int c = 0; c < 8; c++)
            u_s[i * E_STRIDE + j0 + c] = fmaxf(acc[c] + b1_s[j0 + c], 0.f);
        __syncthreads();

        // h = h + u @ w2 + b2   (128 out cols -> 16 per thread)
        float acc2[16];
#pragma unroll
        for (int c = 0; c < 16; c++) acc2[c] = 0.f;
        const int j0b = r << 4;
#pragma unroll 4
        for (int k = 0; k < DHID; k++) {
            float a = u_s[i * E_STRIDE + k];
#pragma unroll
            for (int q = 0; q < 4; q++) {
                float4 w = *(const float4*)(w2_s + k * DN + j0b + 4 * q);
                acc2[4 * q]     = fmaf(a, w.x, acc2[4 * q]);
                acc2[4 * q + 1] = fmaf(a, w.y, acc2[4 * q + 1]);
                acc2[4 * q + 2] = fmaf(a, w.z, acc2[4 * q + 2]);
                acc2[4 * q + 3] = fmaf(a, w.w, acc2[4 * q + 3]);
            }
        }
        if (ok) {
            float* ho = g_h + (size_t)node * DN + j0b;
#pragma unroll
            for (int c = 0; c < 16; c++)
                ho[c] = h_s[i * HS_STRIDE + j0b + c] + acc2[c] + b2_s[j0b + c];
        }
        __syncthreads();
    }
}

// ---------------- readout ----------------
__global__ void readout_accum_kernel(const int* __restrict__ batch) {
    int idx = blockIdx.x * blockDim.x + threadIdx.x;
    if (idx >= N_NODES * DN) return;
    int node = idx >> 7, c = idx & 127;
    int bb = batch[node];
    atomicAdd(&g_gsum[bb * DN + c], g_h[idx]);
    if (c == 0) atomicAdd(&g_gcnt[bb], 1.f);
}

__global__ void ro1_kernel(const float* __restrict__ w, const float* __restrict__ b) {
    __shared__ float gx[DN];
    int g = blockIdx.x, j = threadIdx.x;
    gx[j] = g_gsum[g * DN + j] / fmaxf(g_gcnt[g], 1.f);
    __syncthreads();
    float acc = b[j];
#pragma unroll 8
    for (int k = 0; k < DN; k++) acc = fmaf(gx[k], w[k * DN + j], acc);
    g_rtmp[g * DN + j] = fmaxf(acc, 0.f);
}

__global__ void ro2_kernel(const float* __restrict__ w, const float* __restrict__ b,
                           float* __restrict__ out) {
    __shared__ float gx[DN];
    int g = blockIdx.x, j = threadIdx.x;
    gx[j] = g_rtmp[g * DN + j];
    __syncthreads();
    float acc = b[j];
#pragma unroll 8
    for (int k = 0; k < DN; k++) acc = fmaf(gx[k], w[k * DN + j], acc);
    out[g * DN + j] = acc;
}

// ---------------- host ----------------
static const int EDGE_SMEM_BYTES =
    (DN * DE + (DE + 2 * DN) * DHID + DHID * DE + DHID + DE +
     2 * TE * HS_STRIDE + 3 * TE * E_STRIDE) * 4;   // 192512
static const int NODE_SMEM_BYTES =
    ((DN + DE) * DHID + DHID * DN + DHID + DN +
     TE * HS_STRIDE + 2 * TE * E_STRIDE) * 4;       // 117504

extern "C" void kernel_launch(void* const* d_in, const int* in_sizes, int n_in,
                              void* d_out, int out_size) {
    const float* x       = (const float*)d_in[0];
    const float* ea      = (const float*)d_in[1];
    const int*   eindex  = (const int*)d_in[2];
    const int*   batch   = (const int*)d_in[3];
    const float* lin_x_w = (const float*)d_in[4];
    const float* lin_x_b = (const float*)d_in[5];
    const float* lin_e_w = (const float*)d_in[6];
    const float* lin_e_b = (const float*)d_in[7];
    const float* msg_w   = (const float*)d_in[8];
    const float* pe_w1   = (const float*)d_in[9];
    const float* pe_b1   = (const float*)d_in[10];
    const float* pe_w2   = (const float*)d_in[11];
    const float* pe_b2   = (const float*)d_in[12];
    const float* pv_w1   = (const float*)d_in[13];
    const float* pv_b1   = (const float*)d_in[14];
    const float* pv_w2   = (const float*)d_in[15];
    const float* pv_b2   = (const float*)d_in[16];
    const float* ro_w1   = (const float*)d_in[17];
    const float* ro_b1   = (const float*)d_in[18];
    const float* ro_w2   = (const float*)d_in[19];
    const float* ro_b2   = (const float*)d_in[20];
    const int* src = eindex;
    const int* dst = eindex + N_EDGES;

    cudaFuncSetAttribute(edge_layer_kernel,
                         cudaFuncAttributeMaxDynamicSharedMemorySize, EDGE_SMEM_BYTES);
    cudaFuncSetAttribute(node_layer_kernel,
                         cudaFuncAttributeMaxDynamicSharedMemorySize, NODE_SMEM_BYTES);

    float *p_deg, *p_m, *p_gs, *p_gc;
    cudaGetSymbolAddress((void**)&p_deg, g_deg);
    cudaGetSymbolAddress((void**)&p_m,   g_m);
    cudaGetSymbolAddress((void**)&p_gs,  g_gsum);
    cudaGetSymbolAddress((void**)&p_gc,  g_gcnt);

    node_enc_kernel<<<N_NODES, 128>>>(x, lin_x_w, lin_x_b);
    edge_enc_kernel<<<N_EDGES / 4, 256>>>(ea, lin_e_w, lin_e_b);
    zero_kernel<<<(N_NODES + 255) / 256, 256>>>(p_deg, N_NODES);
    deg_kernel<<<(N_EDGES + 255) / 256, 256>>>(dst);

    for (int l = 0; l < NL; l++) {
        zero_kernel<<<(N_NODES * DE + 255) / 256, 256>>>(p_m, N_NODES * DE);
        edge_layer_kernel<<<148, 256, EDGE_SMEM_BYTES>>>(
            src, dst,
            msg_w + (size_t)l * DN * DE,
            pe_w1 + (size_t)l * (DE + 2 * DN) * DHID,
            pe_b1 + (size_t)l * DHID,
            pe_w2 + (size_t)l * DHID * DE,
            pe_b2 + (size_t)l * DE);
        node_layer_kernel<<<148, 256, NODE_SMEM_BYTES>>>(
            pv_w1 + (size_t)l * (DN + DE) * DHID,
            pv_b1 + (size_t)l * DHID,
            pv_w2 + (size_t)l * DHID * DN,
            pv_b2 + (size_t)l * DN);
    }

    zero_kernel<<<(NB * DN + 255) / 256, 256>>>(p_gs, NB * DN);
    zero_kernel<<<1, 64>>>(p_gc, NB);
    readout_accum_kernel<<<(N_NODES * DN + 255) / 256, 256>>>(batch);
    ro1_kernel<<<NB, DN>>>(ro_w1, ro_b1);
    ro2_kernel<<<NB, DN>>>(ro_w2, ro_b2, (float*)d_out);
}